// round 11
// baseline (speedup 1.0000x reference)
#include <cuda_runtime.h>

// cosine_regularizer: out = (sum(W) - N)/N^2, W = p p^T, p = row-normalized points.
// Identity: sum(W) = || sum_i p_i ||^2.
// R11: single kernel, FULL GRID RESIDENT through the finalize. Every prior epilogue
//      (separate tiny kernel or last-block tail) cost ~5us for ~1us of work: the
//      low-grid issue throttle (vanishes @grid>=148) penalizes a near-idle chip.
//      Now: all 512 CTAs stay resident; block 0 finalizes at full clock while the
//      rest spin on the counter returning to 0 (which also resets state for replay).

constexpr int N_ROWS = 16384;
constexpr int D      = 256;
constexpr int TPB    = 256;                 // 8 warps
constexpr int WARPS  = TPB / 32;
constexpr int NBLK   = 512;                 // single co-resident wave (<= 148*4)
constexpr int ROWS_PER_WARP = 4;
constexpr int NREP   = 16;                  // column-sum replicas (R6 win)

__device__ float        g_rep[NREP][D];   // zero at load; reset by block 0 each run
__device__ unsigned int g_count;          // zero at load; returns to 0 each run

__global__ void __launch_bounds__(TPB, 4)   // cap regs at 64 -> 4 CTAs/SM residency
k_fused(const float* __restrict__ pts, float* __restrict__ out) {
    const int warp = threadIdx.x >> 5;
    const int lane = threadIdx.x & 31;
    const int t    = threadIdx.x;
    const int gw   = blockIdx.x * WARPS + warp;

    // Batch-issue all 8 LDG.128 for this warp's 4 rows.
    float4 v0[ROWS_PER_WARP], v1[ROWS_PER_WARP];
#pragma unroll
    for (int k = 0; k < ROWS_PER_WARP; k++) {
        const int row = gw + k * (NBLK * WARPS);
        const float4* p = reinterpret_cast<const float4*>(pts) + (size_t)row * (D / 4);
        v0[k] = p[lane];        // cols 4*lane   .. +3
        v1[k] = p[32 + lane];   // cols 128+4*lane .. +3
    }

    // Per-row sum of squares; 4 interleaved warp reductions.
    float ss[ROWS_PER_WARP];
#pragma unroll
    for (int k = 0; k < ROWS_PER_WARP; k++) {
        ss[k] = v0[k].x * v0[k].x + v0[k].y * v0[k].y + v0[k].z * v0[k].z + v0[k].w * v0[k].w
              + v1[k].x * v1[k].x + v1[k].y * v1[k].y + v1[k].z * v1[k].z + v1[k].w * v1[k].w;
    }
#pragma unroll
    for (int off = 16; off > 0; off >>= 1) {
#pragma unroll
        for (int k = 0; k < ROWS_PER_WARP; k++)
            ss[k] += __shfl_xor_sync(0xffffffffu, ss[k], off);
    }

    // rnorm * row into per-lane column accumulators.
    float4 a0 = make_float4(0.f, 0.f, 0.f, 0.f);
    float4 a1 = make_float4(0.f, 0.f, 0.f, 0.f);
#pragma unroll
    for (int k = 0; k < ROWS_PER_WARP; k++) {
        const float rn = rsqrtf(ss[k]);
        a0.x += rn * v0[k].x;  a0.y += rn * v0[k].y;
        a0.z += rn * v0[k].z;  a0.w += rn * v0[k].w;
        a1.x += rn * v1[k].x;  a1.y += rn * v1[k].y;
        a1.z += rn * v1[k].z;  a1.w += rn * v1[k].w;
    }

    // Block-reduce 8 warps' column partials via shared.
    __shared__ float sh[WARPS][D];
    float4* shv = reinterpret_cast<float4*>(sh[warp]);
    shv[lane]      = a0;
    shv[32 + lane] = a1;
    __syncthreads();

    float s = sh[0][t];
#pragma unroll
    for (int w = 1; w < WARPS; w++) s += sh[w][t];

    // RED into this block's replica (32 adds/address chip-wide).
    atomicAdd(&g_rep[blockIdx.x & (NREP - 1)][t], s);

    // ---- full-grid-resident finalize ----
    __syncthreads();   // block's REDs precede t0's release-arrive

    if (blockIdx.x == 0) {
        // Arrive, then poll until all 512 blocks have arrived.
        if (t == 0) {
            unsigned int old;
            asm volatile("atom.acq_rel.gpu.global.add.u32 %0, [%1], 1;"
                         : "=r"(old) : "l"(&g_count) : "memory");
            unsigned int c;
            do {
                asm volatile("ld.acquire.gpu.global.u32 %0, [%1];"
                             : "=r"(c) : "l"(&g_count) : "memory");
            } while (c != (unsigned int)NBLK);
        }
        __syncthreads();   // publish acquire to the whole block

        // Fold replicas for this column; reset them for the next replay.
        float v = 0.0f;
#pragma unroll
        for (int r = 0; r < NREP; r++) {
            v += __ldcg(&g_rep[r][t]);
            g_rep[r][t] = 0.0f;
        }

        double d = (double)v * (double)v;
#pragma unroll
        for (int off = 16; off > 0; off >>= 1)
            d += __shfl_xor_sync(0xffffffffu, d, off);

        __shared__ double wsum[WARPS];
        if (lane == 0) wsum[warp] = d;
        __syncthreads();
        if (warp == 0) {
            double x = (lane < WARPS) ? wsum[lane] : 0.0;
#pragma unroll
            for (int off = 4; off > 0; off >>= 1)
                x += __shfl_xor_sync(0xffffffffu, x, off);
            if (lane == 0) {
                const double n = (double)N_ROWS;
                out[0] = (float)((x - n) / (n * n));
            }
        }
        __syncthreads();   // out + resets done before releasing the spinners
        if (t == 0) {
            // Release spinners and restore g_count=0 for the next replay.
            asm volatile("st.release.gpu.global.u32 [%0], %1;"
                         :: "l"(&g_count), "r"(0u) : "memory");
        }
    } else {
        // Arrive, then stay resident (keep the chip busy; low-grid throttle never
        // engages) until block 0 resets the counter to 0.
        if (t == 0) {
            unsigned int old;
            asm volatile("atom.acq_rel.gpu.global.add.u32 %0, [%1], 1;"
                         : "=r"(old) : "l"(&g_count) : "memory");
            unsigned int c;
            do {
                asm volatile("ld.acquire.gpu.global.u32 %0, [%1];"
                             : "=r"(c) : "l"(&g_count) : "memory");
            } while (c != 0u);
        }
        __syncthreads();
    }
}

extern "C" void kernel_launch(void* const* d_in, const int* in_sizes, int n_in,
                              void* d_out, int out_size) {
    const float* pts = (const float*)d_in[0];
    (void)in_sizes; (void)n_in; (void)out_size;
    k_fused<<<NBLK, TPB>>>(pts, (float*)d_out);
}

// round 12
// speedup vs baseline: 1.2286x; 1.2286x over previous
#include <cuda_runtime.h>

// cosine_regularizer: out = (sum(W) - N)/N^2, W = p p^T, p = row-normalized points.
// Identity: sum(W) = || sum_i p_i ||^2.
// R12: fused last-block finalize (R6 baseline) with NBLK 512->256, ROWS_PER_WARP 4->8.
//      Halves end-of-kernel arrivals + per-address RED contention (16 adds/address),
//      halves straggler candidates; 16 batched LDG.128/warp keeps stream BW-bound.

constexpr int N_ROWS = 16384;
constexpr int D      = 256;
constexpr int TPB    = 256;                 // 8 warps
constexpr int WARPS  = TPB / 32;
constexpr int NBLK   = 256;                 // 256*8 warps * 8 rows = 16384 rows
constexpr int ROWS_PER_WARP = 8;
constexpr int NREP   = 16;                  // column-sum replicas (R6 win)

__device__ float        g_rep[NREP][D];   // zero at load; reset by last block each run
__device__ unsigned int g_count;          // zero at load; reset by last block each run

__global__ void __launch_bounds__(TPB, 2)   // ~128-reg budget: all 16 loads batch
k_fused(const float* __restrict__ pts, float* __restrict__ out) {
    const int warp = threadIdx.x >> 5;
    const int lane = threadIdx.x & 31;
    const int t    = threadIdx.x;
    const int gw   = blockIdx.x * WARPS + warp;     // 0..2047

    // Batch-issue all 16 LDG.128 for this warp's 8 rows.
    float4 v0[ROWS_PER_WARP], v1[ROWS_PER_WARP];
#pragma unroll
    for (int k = 0; k < ROWS_PER_WARP; k++) {
        const int row = gw + k * (NBLK * WARPS);    // stride 2048
        const float4* p = reinterpret_cast<const float4*>(pts) + (size_t)row * (D / 4);
        v0[k] = p[lane];        // cols 4*lane   .. +3
        v1[k] = p[32 + lane];   // cols 128+4*lane .. +3
    }

    // Per-row sum of squares; 8 interleaved warp reductions.
    float ss[ROWS_PER_WARP];
#pragma unroll
    for (int k = 0; k < ROWS_PER_WARP; k++) {
        ss[k] = v0[k].x * v0[k].x + v0[k].y * v0[k].y + v0[k].z * v0[k].z + v0[k].w * v0[k].w
              + v1[k].x * v1[k].x + v1[k].y * v1[k].y + v1[k].z * v1[k].z + v1[k].w * v1[k].w;
    }
#pragma unroll
    for (int off = 16; off > 0; off >>= 1) {
#pragma unroll
        for (int k = 0; k < ROWS_PER_WARP; k++)
            ss[k] += __shfl_xor_sync(0xffffffffu, ss[k], off);
    }

    // rnorm * row into per-lane column accumulators.
    float4 a0 = make_float4(0.f, 0.f, 0.f, 0.f);
    float4 a1 = make_float4(0.f, 0.f, 0.f, 0.f);
#pragma unroll
    for (int k = 0; k < ROWS_PER_WARP; k++) {
        const float rn = rsqrtf(ss[k]);
        a0.x += rn * v0[k].x;  a0.y += rn * v0[k].y;
        a0.z += rn * v0[k].z;  a0.w += rn * v0[k].w;
        a1.x += rn * v1[k].x;  a1.y += rn * v1[k].y;
        a1.z += rn * v1[k].z;  a1.w += rn * v1[k].w;
    }

    // Block-reduce 8 warps' column partials via shared.
    __shared__ float sh[WARPS][D];
    float4* shv = reinterpret_cast<float4*>(sh[warp]);
    shv[lane]      = a0;
    shv[32 + lane] = a1;
    __syncthreads();

    float s = sh[0][t];
#pragma unroll
    for (int w = 1; w < WARPS; w++) s += sh[w][t];

    // RED into this block's replica (16 adds/address chip-wide).
    atomicAdd(&g_rep[blockIdx.x & (NREP - 1)][t], s);

    // ---- last-block-done finalize (R6 pattern) ----
    __shared__ unsigned int s_isLast;
    __syncthreads();   // block's REDs happen-before t0's release-arrive
    if (t == 0) {
        unsigned int old;
        asm volatile("atom.acq_rel.gpu.global.add.u32 %0, [%1], 1;"
                     : "=r"(old) : "l"(&g_count) : "memory");
        s_isLast = (old == (unsigned int)(NBLK - 1)) ? 1u : 0u;
    }
    __syncthreads();
    if (!s_isLast) return;

    if (t == 0) g_count = 0u;   // reset for next graph replay

    // Fold replicas for this column; reset them for next replay.
    float v = 0.0f;
#pragma unroll
    for (int r = 0; r < NREP; r++) {
        v += __ldcg(&g_rep[r][t]);
        g_rep[r][t] = 0.0f;
    }

    double d = (double)v * (double)v;
#pragma unroll
    for (int off = 16; off > 0; off >>= 1)
        d += __shfl_xor_sync(0xffffffffu, d, off);

    __shared__ double wsum[WARPS];
    if (lane == 0) wsum[warp] = d;
    __syncthreads();
    if (warp == 0) {
        double x = (lane < WARPS) ? wsum[lane] : 0.0;
#pragma unroll
        for (int off = 4; off > 0; off >>= 1)
            x += __shfl_xor_sync(0xffffffffu, x, off);
        if (lane == 0) {
            const double n = (double)N_ROWS;
            out[0] = (float)((x - n) / (n * n));
        }
    }
}

extern "C" void kernel_launch(void* const* d_in, const int* in_sizes, int n_in,
                              void* d_out, int out_size) {
    const float* pts = (const float*)d_in[0];
    (void)in_sizes; (void)n_in; (void)out_size;
    k_fused<<<NBLK, TPB>>>(pts, (float*)d_out);
}